// round 5
// baseline (speedup 1.0000x reference)
#include <cuda_runtime.h>
#include <cstdint>

// Polar encoder, N=8192, K=4096, BS=8192.
// frozen = [0,4096) => codeword = [y, y] with y = 12-stage Arikan transform of u.
// Transform = tensor product of F over 12 address bits => stages commute and
// address bits map freely onto storage dimensions.
//
// Storage map (one warp = one row): u float index a (12 bits),
//   a = 128*q + 4*lane + c   (q = load instr 0..31, c = float4 component)
//   word t = q>>3 (a11,a10), bit = 4*(q&7)+c (a9..a7, a1..a0), lane = a6..a2.
// Stage mechanisms (order arbitrary — stages commute):
//   a10,a11    -> intra-thread word XOR      (done FIRST, right after pack)
//   a0,a1      -> intra-word XOR, shifts 1,2
//   a7,a8,a9   -> intra-word XOR, shifts 4,8,16
//   a2..a6     -> __shfl_xor masks 1..16
// Per-word epilogue: word t finishes its 5 shuffles and stores immediately,
// overlapping SHFL/ALU of later words with STG drain of earlier ones.
// .cs streaming hints on all global traffic (pure stream, no reuse).

#define NN   8192
#define KK   4096
#define BSZ  8192

__global__ __launch_bounds__(128)
void polar_encode_kernel(const float4* __restrict__ u4, float* __restrict__ out) {
    const int warp = threadIdx.x >> 5;
    const int lane = threadIdx.x & 31;
    const int row  = blockIdx.x * 4 + warp;

    const float4* __restrict__ urow4 = u4 + (size_t)row * (KK / 4);

    unsigned w[4];

    // ---- 1. Streaming loads (coalesced float4) + arithmetic bit-pack.
    //         Values are exactly 0.0f/1.0f, so nib = x + 2y + 4z + 8w is exact.
    #pragma unroll
    for (int t = 0; t < 4; t++) {
        float4 f[8];
        #pragma unroll
        for (int r = 0; r < 8; r++)
            f[r] = __ldcs(&urow4[(t * 8 + r) * 32 + lane]);  // 8 independent 16B loads
        unsigned acc = 0u;
        #pragma unroll
        for (int r = 0; r < 8; r++) {
            float nf = fmaf(8.0f, f[r].w,
                       fmaf(4.0f, f[r].z,
                       fmaf(2.0f, f[r].y, f[r].x)));
            acc |= ((unsigned)__float2int_rn(nf)) << (4 * r);
        }
        w[t] = acc;
    }

    // ---- 2. Intra-thread word stages first: address bits a10, a11.
    w[0] ^= w[1];  w[2] ^= w[3];   // a10
    w[0] ^= w[2];  w[1] ^= w[3];   // a11

    float4* __restrict__ o0 = (float4*)(out + (size_t)row * NN);
    float4* __restrict__ o1 = (float4*)(out + (size_t)row * NN + KK);
    const unsigned ONE = 0x3F800000u;

    // ---- 3. Per-word: intra-word stages, cross-lane stages, expand, store.
    #pragma unroll
    for (int t = 0; t < 4; t++) {
        unsigned x = w[t];
        // address bits a0,a1 (shifts 1,2) and a7,a8,a9 (shifts 4,8,16)
        x ^= (x >> 1)  & 0x55555555u;
        x ^= (x >> 2)  & 0x33333333u;
        x ^= (x >> 4)  & 0x0F0F0F0Fu;
        x ^= (x >> 8)  & 0x00FF00FFu;
        x ^= (x >> 16);
        // address bits a2..a6: shfl_xor masks 1..16
        #pragma unroll
        for (int m = 1; m <= 16; m <<= 1) {
            const unsigned p = __shfl_xor_sync(0xffffffffu, x, m);
            if ((lane & m) == 0) x ^= p;
        }
        // expand bits -> floats; store both halves (codeword = [y, y]).
        #pragma unroll
        for (int r = 0; r < 8; r++) {
            const unsigned nib = (x >> (4 * r)) & 0xFu;
            float4 f;
            f.x = __uint_as_float((nib & 1u)        * ONE);
            f.y = __uint_as_float(((nib >> 1) & 1u) * ONE);
            f.z = __uint_as_float(((nib >> 2) & 1u) * ONE);
            f.w = __uint_as_float(((nib >> 3) & 1u) * ONE);
            const int j = t * 8 + r;
            __stcs(&o0[j * 32 + lane], f);
            __stcs(&o1[j * 32 + lane], f);
        }
    }
}

extern "C" void kernel_launch(void* const* d_in, const int* in_sizes, int n_in,
                              void* d_out, int out_size) {
    // d_in[0]: u (float32, BS*K); d_in[1]/d_in[2]: structurally constant, unused.
    const float4* u4 = (const float4*)d_in[0];
    float* out = (float*)d_out;
    (void)in_sizes; (void)n_in; (void)out_size;

    polar_encode_kernel<<<BSZ / 4, 128>>>(u4, out);
}

// round 6
// speedup vs baseline: 1.1860x; 1.1860x over previous
#include <cuda_runtime.h>
#include <cstdint>

// Polar encoder, N=8192, K=4096, BS=8192.
// frozen = [0,4096) => codeword = [y, y] with y = 12-stage Arikan transform of u.
// Transform = tensor product of F over 12 address bits => stages commute and
// address bits map freely onto storage dimensions.
//
// Storage map (one warp = one row): u float index a (12 bits),
//   a = 128*q + 4*lane + c   (q = load instr 0..31, c = float4 component)
//   word t = q>>3 (a11,a10), bit = 4*(q&7)+c (a9..a7, a1..a0), lane = a6..a2.
// Stage mechanisms:
//   a0,a1      -> intra-word XOR, shifts 1,2
//   a7,a8,a9   -> intra-word XOR, shifts 4,8,16
//   a2..a6     -> __shfl_xor masks 1..16
//   a10,a11    -> intra-thread word XOR
//
// R6 change vs R4: loads are explicitly batched 16-deep in registers before
// packing (two batches), raising per-thread MLP from ~4 (regs=38 in R4 => ptxas
// had serialized the loads) to ~16, to hide the 577-cycle DRAM latency.

#define NN   8192
#define KK   4096
#define BSZ  8192

__global__ __launch_bounds__(128)
void polar_encode_kernel(const float4* __restrict__ u4, float* __restrict__ out) {
    const int warp = threadIdx.x >> 5;
    const int lane = threadIdx.x & 31;
    const int row  = blockIdx.x * 4 + warp;

    const float4* __restrict__ urow4 = u4 + (size_t)row * (KK / 4);

    unsigned w[4];

    // ---- 1. Deep-batched loads + arithmetic bit-pack.
    //         Values are exactly 0.0f/1.0f, so nib = x + 2y + 4z + 8w is exact.
    #pragma unroll
    for (int h = 0; h < 2; h++) {               // t = 2h, 2h+1
        float4 f[16];                            // 16 loads in flight (64 regs)
        #pragma unroll
        for (int r = 0; r < 16; r++)
            f[r] = urow4[(h * 16 + r) * 32 + lane];
        #pragma unroll
        for (int tt = 0; tt < 2; tt++) {
            unsigned acc = 0u;
            #pragma unroll
            for (int r = 0; r < 8; r++) {
                const float4 v = f[tt * 8 + r];
                float nf = fmaf(8.0f, v.w,
                           fmaf(4.0f, v.z,
                           fmaf(2.0f, v.y, v.x)));
                acc |= ((unsigned)__float2int_rn(nf)) << (4 * r);
            }
            w[h * 2 + tt] = acc;
        }
    }

    // ---- 2. Intra-word stages: address bits a0,a1 (shift 1,2), a7,a8,a9
    //         (shift 4,8,16).
    #pragma unroll
    for (int t = 0; t < 4; t++) {
        unsigned x = w[t];
        x ^= (x >> 1)  & 0x55555555u;
        x ^= (x >> 2)  & 0x33333333u;
        x ^= (x >> 4)  & 0x0F0F0F0Fu;
        x ^= (x >> 8)  & 0x00FF00FFu;
        x ^= (x >> 16);
        w[t] = x;
    }

    // ---- 3. Cross-lane stages: address bits a2..a6 (shfl_xor masks 1..16).
    #pragma unroll
    for (int m = 1; m <= 16; m <<= 1) {
        #pragma unroll
        for (int t = 0; t < 4; t++) {
            const unsigned p = __shfl_xor_sync(0xffffffffu, w[t], m);
            if ((lane & m) == 0) w[t] ^= p;
        }
    }

    // ---- 4. Intra-thread word stages: address bits a10, a11.
    w[0] ^= w[1];  w[2] ^= w[3];   // a10
    w[0] ^= w[2];  w[1] ^= w[3];   // a11

    // ---- 5. Expand bits -> floats, store both halves (codeword = [y, y]).
    float4* __restrict__ o0 = (float4*)(out + (size_t)row * NN);
    float4* __restrict__ o1 = (float4*)(out + (size_t)row * NN + KK);

    const unsigned ONE = 0x3F800000u;
    #pragma unroll
    for (int t = 0; t < 4; t++) {
        #pragma unroll
        for (int r = 0; r < 8; r++) {
            const unsigned nib = (w[t] >> (4 * r)) & 0xFu;
            float4 f;
            f.x = __uint_as_float((nib & 1u)        * ONE);
            f.y = __uint_as_float(((nib >> 1) & 1u) * ONE);
            f.z = __uint_as_float(((nib >> 2) & 1u) * ONE);
            f.w = __uint_as_float(((nib >> 3) & 1u) * ONE);
            const int j = t * 8 + r;
            o0[j * 32 + lane] = f;
            o1[j * 32 + lane] = f;
        }
    }
}

extern "C" void kernel_launch(void* const* d_in, const int* in_sizes, int n_in,
                              void* d_out, int out_size) {
    // d_in[0]: u (float32, BS*K); d_in[1]/d_in[2]: structurally constant, unused.
    const float4* u4 = (const float4*)d_in[0];
    float* out = (float*)d_out;
    (void)in_sizes; (void)n_in; (void)out_size;

    polar_encode_kernel<<<BSZ / 4, 128>>>(u4, out);
}